// round 9
// baseline (speedup 1.0000x reference)
#include <cuda_runtime.h>
#include <cuda_bf16.h>
#include <cstdint>

#define EMBED 100
#define BATCH 8192
#define MAT_FLOATS (EMBED * EMBED)   // 10000
#define MAT_BYTES  (MAT_FLOATS * 4)  // 40000, multiple of 16
#define VEC4_PER_MAT 2500
#define F4_PER_ROW   25
#define NTHREADS     256
#define ITERS        10

// Canonical mbarrier wait (from ptx_helpers.cuh): try_wait fast path + bounded
// suspended retry loop. Each retry has a 10M ns suspend hint; loop re-issues
// until the phase flips, so no unbounded busy-spin.
#define MBARRIER_WAIT_PARITY(mbar_smem_addr, phase_parity) do { \
    uint32_t _mbar = (uint32_t)(mbar_smem_addr); \
    uint32_t _parity = (uint32_t)(phase_parity); \
    uint32_t _done; \
    asm volatile( \
        "{\n\t" \
        ".reg .pred p;\n\t" \
        "mbarrier.try_wait.parity.acquire.cta.shared::cta.b64 p, [%1], %2;\n\t" \
        "selp.b32 %0, 1, 0, p;\n\t" \
        "}" \
        : "=r"(_done) : "r"(_mbar), "r"(_parity) : "memory"); \
    if (!_done) { \
        asm volatile( \
            "{\n\t" \
            ".reg .pred P1;\n\t" \
            "WAIT_LOOP_%=:\n\t" \
            "mbarrier.try_wait.parity.acquire.cta.shared::cta.b64 P1, [%0], %1, 0x989680;\n\t" \
            "@P1 bra.uni WAIT_DONE_%=;\n\t" \
            "bra.uni WAIT_LOOP_%=;\n\t" \
            "WAIT_DONE_%=:\n\t" \
            "}" \
            :: "r"(_mbar), "r"(_parity) : "memory"); \
    } \
} while(0)

__global__ __launch_bounds__(NTHREADS)
void matrix_skipgram_kernel(const int* __restrict__ X_argument,
                            const int* __restrict__ X_functor,
                            const int* __restrict__ X_context,
                            const float* __restrict__ noun_matrix,
                            const float* __restrict__ functor_table,
                            const float* __restrict__ context_table,
                            float* __restrict__ out)
{
    __shared__ alignas(16) float s_mat[MAT_FLOATS];   // 40000 B
    __shared__ float s_arg[EMBED];
    __shared__ float s_ctx[EMBED];
    __shared__ float s_red[NTHREADS / 32];
    __shared__ alignas(8) unsigned long long s_mbar;

    const int b = blockIdx.x;
    const int t = threadIdx.x;

    const uint32_t mbar_addr = (uint32_t)__cvta_generic_to_shared(&s_mbar);
    const uint32_t mat_addr  = (uint32_t)__cvta_generic_to_shared(s_mat);

    if (t == 0) {
        asm volatile("mbarrier.init.shared.b64 [%0], %1;"
                     :: "r"(mbar_addr), "r"(1) : "memory");
        // Order the generic-proxy init before async-proxy use of the barrier.
        asm volatile("fence.proxy.async.shared::cta;" ::: "memory");
    }
    __syncthreads();

    // One bulk async copy: entire 40KB functor matrix -> smem.
    if (t == 0) {
        const float* src = functor_table + (size_t)X_functor[b] * MAT_FLOATS;
        asm volatile("mbarrier.arrive.expect_tx.shared.b64 _, [%0], %1;"
                     :: "r"(mbar_addr), "r"((uint32_t)MAT_BYTES) : "memory");
        asm volatile("cp.async.bulk.shared::cta.global.mbarrier::complete_tx::bytes "
                     "[%0], [%1], %2, [%3];"
                     :: "r"(mat_addr), "l"(src), "r"((uint32_t)MAT_BYTES), "r"(mbar_addr)
                     : "memory");
    }

    // Stage vectors while the bulk copy is in flight.
    {
        const float* av = noun_matrix   + (size_t)X_argument[b] * EMBED;
        const float* cv = context_table + (size_t)X_context[b]  * EMBED;
        if (t < EMBED) {
            s_arg[t] = av[t];
            s_ctx[t] = cv[t];
        }
    }
    __syncthreads();   // s_arg/s_ctx ready

    // Wait for the TMA bulk copy (phase 0: barrier freshly init'd this launch).
    MBARRIER_WAIT_PARITY(mbar_addr, 0);

    // Compute from smem: conflict-free LDS.128 stream.
    const float4* __restrict__ Ms = reinterpret_cast<const float4*>(s_mat);
    float acc = 0.0f;
    #pragma unroll
    for (int it = 0; it < ITERS; ++it) {
        const int k = t + it * NTHREADS;
        if (k < VEC4_PER_MAT) {
            const int i  = k / F4_PER_ROW;
            const int j4 = (k - i * F4_PER_ROW) * 4;
            const float4 m = Ms[k];
            float dot = m.x * s_arg[j4]
                      + m.y * s_arg[j4 + 1]
                      + m.z * s_arg[j4 + 2]
                      + m.w * s_arg[j4 + 3];
            acc = fmaf(s_ctx[i], dot, acc);
        }
    }

    // Warp reduction
    #pragma unroll
    for (int o = 16; o > 0; o >>= 1)
        acc += __shfl_xor_sync(0xFFFFFFFFu, acc, o);

    if ((t & 31) == 0)
        s_red[t >> 5] = acc;
    __syncthreads();

    if (t < (NTHREADS / 32)) {
        acc = s_red[t];
        #pragma unroll
        for (int o = (NTHREADS / 64); o > 0; o >>= 1)
            acc += __shfl_xor_sync(0xFFu, acc, o);
        if (t == 0)
            out[b] = acc;
    }
}

extern "C" void kernel_launch(void* const* d_in, const int* in_sizes, int n_in,
                              void* d_out, int out_size)
{
    const int*   X_argument    = (const int*)  d_in[0];
    const int*   X_functor     = (const int*)  d_in[1];
    const int*   X_context     = (const int*)  d_in[2];
    const float* noun_matrix   = (const float*)d_in[3];
    const float* functor_table = (const float*)d_in[4];
    const float* context_table = (const float*)d_in[5];
    float* out = (float*)d_out;

    matrix_skipgram_kernel<<<BATCH, NTHREADS>>>(
        X_argument, X_functor, X_context,
        noun_matrix, functor_table, context_table, out);
}